// round 16
// baseline (speedup 1.0000x reference)
#include <cuda_runtime.h>
#include <cuda_fp16.h>

#define THREADS   256
#define BLOCKS    888           // 148 SMs x 6 blocks  == exactly one wave
#define TOTAL_Q   32768
#define CH        8             // rows per inner chunk

static __device__ __forceinline__ unsigned dup16(float x) {
    const unsigned h = __half_as_ushort(__float2half_rn(x));
    return h * 0x10001u;
}
static __device__ __forceinline__ unsigned pack16(float lo, float hi) {
    const unsigned a = __half_as_ushort(__float2half_rn(lo));
    const unsigned b = __half_as_ushort(__float2half_rn(hi));
    return a | (b << 16);
}
static __device__ __forceinline__ unsigned hadd2u(unsigned a, unsigned b) {
    __half2 r = __hadd2(*(const __half2*)&a, *(const __half2*)&b);
    return *(unsigned*)&r;
}
static __device__ __forceinline__ unsigned hfma2u(unsigned a, unsigned b, unsigned c) {
    __half2 r = __hfma2(*(const __half2*)&a, *(const __half2*)&b, *(const __half2*)&c);
    return *(unsigned*)&r;
}
static __device__ __forceinline__ __half2 u2h(unsigned a) { return *(const __half2*)&a; }

// C[bq, t] = 5 * sum_d |qb[d] - tb[d]|  -  p_{label[t]}(bq)
__global__ __launch_bounds__(THREADS, 6)   // guarantee 6 blocks/SM -> single wave
void hm_cost_kernel(const float* __restrict__ logits,   // [32768, 2]
                    const float* __restrict__ qboxes,   // [32768, 6]
                    const int*   __restrict__ tlabels,  // [1024]
                    const float* __restrict__ tboxes,   // [1024, 6]
                    float*       __restrict__ out)      // [32768, 1024]
{
    // double-buffered per-chunk query data: 8 u32 fields per row
    __shared__ __align__(16) unsigned sq[2][CH * 8];

    const int tx = threadIdx.x;

    // contiguous row range for this block: 36 or 37 rows (1-row imbalance)
    const int r0 = (int)(((unsigned long long)blockIdx.x       * TOTAL_Q) / BLOCKS);
    const int r1 = (int)(((unsigned long long)(blockIdx.x + 1) * TOTAL_Q) / BLOCKS);

    // ---- per-thread targets: 4 rows, fp16x2 packed & negated + 2 label masks ----
    unsigned nt[2][6];
    unsigned lmask[2];
    {
        const float4* tb4 = (const float4*)(tboxes + (size_t)tx * 24);
        const float4 v0 = tb4[0], v1 = tb4[1], v2 = tb4[2];
        const float4 v3 = tb4[3], v4 = tb4[4], v5 = tb4[5];
        const float q0_[6] = {v0.x, v0.y, v0.z, v0.w, v1.x, v1.y};
        const float q1_[6] = {v1.z, v1.w, v2.x, v2.y, v2.z, v2.w};
        const float q2_[6] = {v3.x, v3.y, v3.z, v3.w, v4.x, v4.y};
        const float q3_[6] = {v4.z, v4.w, v5.x, v5.y, v5.z, v5.w};
#pragma unroll
        for (int d = 0; d < 6; ++d) {
            nt[0][d] = pack16(-q0_[d], -q1_[d]);
            nt[1][d] = pack16(-q2_[d], -q3_[d]);
        }
        const int4 lb = *(const int4*)(tlabels + tx * 4);
        lmask[0] = (lb.x ? 0x0000FFFFu : 0u) | (lb.y ? 0xFFFF0000u : 0u);
        lmask[1] = (lb.z ? 0x0000FFFFu : 0u) | (lb.w ? 0xFFFF0000u : 0u);
    }

    // ---- chunk preload helper (threads 0 .. n*8-1) ----
#define PRELOAD(ROW0, N, BUF)                                                  \
    do {                                                                       \
        if (tx < (N) * 8) {                                                    \
            const int q = tx >> 3;                                             \
            const int f = tx & 7;                                              \
            const int gq = (ROW0) + q;                                         \
            unsigned v;                                                        \
            if (f < 6) {                                                       \
                v = dup16(qboxes[gq * 6 + f]);                                 \
            } else {                                                           \
                const float l0 = logits[gq * 2 + 0];                           \
                const float l1 = logits[gq * 2 + 1];                           \
                const float p0 = 1.0f / (1.0f + __expf(l1 - l0));              \
                v = dup16((f == 6) ? -p0 : (p0 - 1.0f));                       \
            }                                                                  \
            sq[BUF][q * 8 + f] = v;                                            \
        }                                                                      \
    } while (0)

    const unsigned five2 = 0x45004500u;   // fp16x2 (5.0, 5.0)

    int buf = 0;
    int n0 = min(CH, r1 - r0);
    PRELOAD(r0, n0, 0);
    __syncthreads();

    for (int r = r0; r < r1; r += CH) {
        const int n = min(CH, r1 - r);
        const int rn = r + CH;
        if (rn < r1) {
            PRELOAD(rn, min(CH, r1 - rn), buf ^ 1);   // overlap with compute below
        }

        char* obase = (char*)out + ((size_t)r * 1024 + 4 * tx) * sizeof(float);
#pragma unroll 8
        for (int q = 0; q < n; ++q) {
            const uint4 A = *(const uint4*)(&sq[buf][q * 8]);       // LDS.128
            const uint4 B = *(const uint4*)(&sq[buf][q * 8 + 4]);   // LDS.128
            const unsigned d0 = A.x, d1 = A.y, d2 = A.z, d3 = A.w, d4 = B.x, d5 = B.y;
            const unsigned mp0 = B.z, mp1 = B.w;

            unsigned r16[2];
#pragma unroll
            for (int p = 0; p < 2; ++p) {
                const unsigned a0 = hadd2u(d0, nt[p][0]) & 0x7FFF7FFFu;
                const unsigned a1 = hadd2u(d1, nt[p][1]) & 0x7FFF7FFFu;
                const unsigned a2 = hadd2u(d2, nt[p][2]) & 0x7FFF7FFFu;
                const unsigned a3 = hadd2u(d3, nt[p][3]) & 0x7FFF7FFFu;
                const unsigned a4 = hadd2u(d4, nt[p][4]) & 0x7FFF7FFFu;
                const unsigned a5 = hadd2u(d5, nt[p][5]) & 0x7FFF7FFFu;
                const unsigned s  = hadd2u(hadd2u(hadd2u(a0, a1), hadd2u(a2, a3)),
                                           hadd2u(a4, a5));
                const unsigned cc = (lmask[p] & mp1) | (~lmask[p] & mp0);  // 1 LOP3
                r16[p] = hfma2u(s, five2, cc);
            }
            const float2 fa = __half22float2(u2h(r16[0]));
            const float2 fb = __half22float2(u2h(r16[1]));
            asm volatile("st.global.cs.v4.f32 [%0], {%1, %2, %3, %4};"
                         :: "l"(obase + q * 4096),
                            "f"(fa.x), "f"(fa.y), "f"(fb.x), "f"(fb.y)
                         : "memory");
        }
        // one sync per chunk: publishes next buffer's preload AND guards this
        // buffer against being overwritten in the iteration after next
        __syncthreads();
        buf ^= 1;
    }
#undef PRELOAD
}

extern "C" void kernel_launch(void* const* d_in, const int* in_sizes, int n_in,
                              void* d_out, int out_size)
{
    const float* logits  = (const float*)d_in[0];  // (16, 2048, 2) f32
    const float* qboxes  = (const float*)d_in[1];  // (16, 2048, 6) f32
    const int*   tlabels = (const int*)  d_in[2];  // (1024,) int32
    const float* tboxes  = (const float*)d_in[3];  // (1024, 6) f32

    hm_cost_kernel<<<BLOCKS, THREADS>>>(logits, qboxes, tlabels, tboxes, (float*)d_out);
}